// round 2
// baseline (speedup 1.0000x reference)
#include <cuda_runtime.h>
#include <math.h>

#define N       8192
#define DX      256
#define DZ      64
#define KK      5
#define EPSF    1e-7f

#define TI      128
#define TJ      128
#define BK      16
#define JSPLIT  4
#define JCHUNK  (N / JSPLIT)     // 2048
#define JTILES  (JCHUNK / TJ)    // 16
#define IBLOCKS (N / TI)         // 64
#define KCHUNKS (DX / BK)        // 16
#define TIP     (TI + 4)         // padded smem row for A/B tiles
#define TJP     (TJ + 1)         // padded smem row for D tile (conflict-free column scan)

// Scratch (static device globals; no runtime allocation)
__device__ float g_sqX[N];
__device__ float g_topv[JSPLIT * N * KK];
__device__ int   g_topi[JSPLIT * N * KK];
__device__ float g_partial[N / 8];

// ---------------- kernel 1: row squared norms of X ----------------
__global__ void sqx_kernel(const float* __restrict__ X) {
    int row  = blockIdx.x * 8 + (threadIdx.x >> 5);
    int lane = threadIdx.x & 31;
    const float4* xr = reinterpret_cast<const float4*>(X + (size_t)row * DX);
    float s = 0.f;
#pragma unroll
    for (int t = 0; t < 2; ++t) {
        float4 v = xr[lane + 32 * t];
        s += v.x * v.x + v.y * v.y + v.z * v.z + v.w * v.w;
    }
#pragma unroll
    for (int o = 16; o > 0; o >>= 1) s += __shfl_down_sync(0xffffffffu, s, o);
    if (lane == 0) g_sqX[row] = s;
}

// ---------------- top-5 sorted insert (all static indexing) ----------------
__device__ __forceinline__ void topk_insert(float (&bv)[KK], int (&bi)[KK], float v, int j) {
    if (v < bv[KK - 1]) {
        bv[KK - 1] = v; bi[KK - 1] = j;
#pragma unroll
        for (int q = KK - 1; q > 0; --q) {
            if (bv[q] < bv[q - 1]) {
                float tv = bv[q]; bv[q] = bv[q - 1]; bv[q - 1] = tv;
                int   tj = bi[q]; bi[q] = bi[q - 1]; bi[q - 1] = tj;
            }
        }
    }
}

// ---------------- kernel 2: fused Gram + per-row top-5 ----------------
// Each CTA: 128 i-rows x one j-slice of 2048. Ds holds halfval = 0.5*sq[j] - dot.
// d2 = sq[i] + 2*halfval (same ordering per row, so top-5 on halfval is valid).
__global__ __launch_bounds__(256, 2)
void knn_kernel(const float* __restrict__ X) {
    extern __shared__ float smem[];
    float* As  = smem;                       // [2][BK][TIP]
    float* Bs  = As + 2 * BK * TIP;          // [2][BK][TIP]
    float* Ds  = Bs + 2 * BK * TIP;          // [TI][TJP]
    float* SqJ = Ds + TI * TJP;              // [TJ]

    const int tid = threadIdx.x;
    const int tx  = tid & 15;
    const int ty  = tid >> 4;
    const int i0    = blockIdx.x * TI;
    const int jbase = blockIdx.y * JCHUNK;
    const float FINF = __int_as_float(0x7f800000);

    // persistent per-row top-5 (scanner threads tid < TI own row i0+tid)
    float bv[KK]; int bi[KK];
#pragma unroll
    for (int q = 0; q < KK; ++q) { bv[q] = FINF; bi[q] = 0; }

    for (int jt = 0; jt < JTILES; ++jt) {
        const int j0 = jbase + jt * TJ;

        if (tid < TJ) SqJ[tid] = g_sqX[j0 + tid];

        float c[8][8];
#pragma unroll
        for (int r = 0; r < 8; ++r)
#pragma unroll
            for (int cc = 0; cc < 8; ++cc) c[r][cc] = 0.f;

        // ---- prologue: load k-chunk 0 into buffer 0 ----
        {
            int idx0 = tid;        int r0 = idx0 >> 2, q0 = idx0 & 3;
            int idx1 = tid + 256;  int r1 = idx1 >> 2, q1 = idx1 & 3;
            float4 a0 = *(const float4*)(X + (size_t)(i0 + r0) * DX + 4 * q0);
            float4 a1 = *(const float4*)(X + (size_t)(i0 + r1) * DX + 4 * q1);
            float4 b0 = *(const float4*)(X + (size_t)(j0 + r0) * DX + 4 * q0);
            float4 b1 = *(const float4*)(X + (size_t)(j0 + r1) * DX + 4 * q1);
            float* da0 = As + (4 * q0) * TIP + r0;
            da0[0] = a0.x; da0[TIP] = a0.y; da0[2 * TIP] = a0.z; da0[3 * TIP] = a0.w;
            float* da1 = As + (4 * q1) * TIP + r1;
            da1[0] = a1.x; da1[TIP] = a1.y; da1[2 * TIP] = a1.z; da1[3 * TIP] = a1.w;
            float* db0 = Bs + (4 * q0) * TIP + r0;
            db0[0] = b0.x; db0[TIP] = b0.y; db0[2 * TIP] = b0.z; db0[3 * TIP] = b0.w;
            float* db1 = Bs + (4 * q1) * TIP + r1;
            db1[0] = b1.x; db1[TIP] = b1.y; db1[2 * TIP] = b1.z; db1[3 * TIP] = b1.w;
        }
        __syncthreads();

        // ---- main k loop with double buffering ----
        for (int kc = 0; kc < KCHUNKS; ++kc) {
            const int cur = kc & 1;
            float4 pa0, pa1, pb0, pb1;
            int r0 = 0, q0 = 0, r1 = 0, q1 = 0;
            if (kc + 1 < KCHUNKS) {
                const int kk = (kc + 1) * BK;
                int idx0 = tid;        r0 = idx0 >> 2; q0 = idx0 & 3;
                int idx1 = tid + 256;  r1 = idx1 >> 2; q1 = idx1 & 3;
                pa0 = *(const float4*)(X + (size_t)(i0 + r0) * DX + kk + 4 * q0);
                pa1 = *(const float4*)(X + (size_t)(i0 + r1) * DX + kk + 4 * q1);
                pb0 = *(const float4*)(X + (size_t)(j0 + r0) * DX + kk + 4 * q0);
                pb1 = *(const float4*)(X + (size_t)(j0 + r1) * DX + kk + 4 * q1);
            }
#pragma unroll
            for (int k = 0; k < BK; ++k) {
                float a[8], b[8];
                const float* Ak = As + (cur * BK + k) * TIP;
                const float* Bk = Bs + (cur * BK + k) * TIP;
                *(float4*)&a[0] = *(const float4*)&Ak[ty * 4];
                *(float4*)&a[4] = *(const float4*)&Ak[64 + ty * 4];
                *(float4*)&b[0] = *(const float4*)&Bk[tx * 4];
                *(float4*)&b[4] = *(const float4*)&Bk[64 + tx * 4];
#pragma unroll
                for (int r = 0; r < 8; ++r)
#pragma unroll
                    for (int cc = 0; cc < 8; ++cc)
                        c[r][cc] = fmaf(a[r], b[cc], c[r][cc]);
            }
            if (kc + 1 < KCHUNKS) {
                const int nb = cur ^ 1;
                float* da0 = As + (nb * BK + 4 * q0) * TIP + r0;
                da0[0] = pa0.x; da0[TIP] = pa0.y; da0[2 * TIP] = pa0.z; da0[3 * TIP] = pa0.w;
                float* da1 = As + (nb * BK + 4 * q1) * TIP + r1;
                da1[0] = pa1.x; da1[TIP] = pa1.y; da1[2 * TIP] = pa1.z; da1[3 * TIP] = pa1.w;
                float* db0 = Bs + (nb * BK + 4 * q0) * TIP + r0;
                db0[0] = pb0.x; db0[TIP] = pb0.y; db0[2 * TIP] = pb0.z; db0[3 * TIP] = pb0.w;
                float* db1 = Bs + (nb * BK + 4 * q1) * TIP + r1;
                db1[0] = pb1.x; db1[TIP] = pb1.y; db1[2 * TIP] = pb1.z; db1[3 * TIP] = pb1.w;
            }
            __syncthreads();
        }

        // ---- writer phase: halfval = 0.5*sq[j] - dot into Ds ----
        {
            float sjc[8];
#pragma unroll
            for (int v = 0; v < 4; ++v) {
                sjc[v]     = SqJ[tx * 4 + v];
                sjc[4 + v] = SqJ[64 + tx * 4 + v];
            }
#pragma unroll
            for (int r = 0; r < 8; ++r) {
                int row = (r < 4) ? (ty * 4 + r) : (64 + ty * 4 + (r - 4));
                float* drow = Ds + row * TJP;
#pragma unroll
                for (int cc = 0; cc < 8; ++cc) {
                    int col = (cc < 4) ? (tx * 4 + cc) : (64 + tx * 4 + (cc - 4));
                    drow[col] = fmaf(0.5f, sjc[cc], -c[r][cc]);
                }
            }
        }
        __syncthreads();

        // ---- scan phase: 128 threads, one per row, persistent top-5 ----
        if (tid < TI) {
            const float* drow = Ds + tid * TJP;
            const int selfcol = (i0 + tid) - j0;   // in [0,TJ) only if self in tile
#pragma unroll 4
            for (int e = 0; e < TJ; ++e) {
                float v = drow[e];
                if (v < bv[KK - 1] && e != selfcol)
                    topk_insert(bv, bi, v, j0 + e);
            }
        }
        __syncthreads();
    }

    if (tid < TI) {
        const int row  = i0 + tid;
        const int base = (blockIdx.y * N + row) * KK;
#pragma unroll
        for (int q = 0; q < KK; ++q) {
            g_topv[base + q] = bv[q];
            g_topi[base + q] = bi[q];
        }
    }
}

// ---------------- kernel 3: merge slices, LID_X / LID_Z, per-block partial ----
__global__ void final_kernel(const float* __restrict__ Z) {
    const int warp = threadIdx.x >> 5;
    const int lane = threadIdx.x & 31;
    const int row  = blockIdx.x * 8 + warp;
    const float FINF = __int_as_float(0x7f800000);

    // merge JSPLIT*5 candidates (all lanes redundantly: broadcast loads, no divergence)
    float bv[KK]; int bi[KK];
#pragma unroll
    for (int q = 0; q < KK; ++q) { bv[q] = FINF; bi[q] = 0; }
    for (int s = 0; s < JSPLIT; ++s) {
        const int base = (s * N + row) * KK;
#pragma unroll
        for (int q = 0; q < KK; ++q)
            topk_insert(bv, bi, g_topv[base + q], g_topi[base + q]);
    }

    const float sqi = g_sqX[row];
    float vx[KK];
#pragma unroll
    for (int q = 0; q < KK; ++q) {
        float d2 = fmaxf(fmaf(2.f, bv[q], sqi), 0.f);
        vx[q] = sqrtf(d2) + EPSF;
    }
    float lidX = 0.f;
    {
        float l4 = log10f(vx[KK - 1]);
#pragma unroll
        for (int q = 0; q < KK; ++q) lidX += l4 - log10f(vx[q]);
    }

    // Z distances to the 5 X-neighbors (warp-parallel over 64 dims)
    const float zi0 = Z[(size_t)row * DZ + lane];
    const float zi1 = Z[(size_t)row * DZ + 32 + lane];
    float ez[KK];
#pragma unroll
    for (int q = 0; q < KK; ++q) {
        const int j = bi[q];
        float d0 = zi0 - Z[(size_t)j * DZ + lane];
        float d1 = zi1 - Z[(size_t)j * DZ + 32 + lane];
        float s = d0 * d0 + d1 * d1;
#pragma unroll
        for (int o = 16; o > 0; o >>= 1) s += __shfl_xor_sync(0xffffffffu, s, o);
        ez[q] = sqrtf(s) + EPSF;
    }
    float lidZ = 0.f;
    {
        float l4 = log10f(ez[KK - 1]);
#pragma unroll
        for (int q = 0; q < KK; ++q) lidZ += l4 - log10f(ez[q]);
    }

    float diff = lidX - lidZ;
    float val  = diff * diff;

    __shared__ float ws[8];
    if (lane == 0) ws[warp] = val;
    __syncthreads();
    if (threadIdx.x == 0) {
        float s = 0.f;
#pragma unroll
        for (int w = 0; w < 8; ++w) s += ws[w];
        g_partial[blockIdx.x] = s;
    }
}

// ---------------- kernel 4: deterministic final reduction ----------------
__global__ void reduce_kernel(float* __restrict__ out) {
    __shared__ float sh[1024];
    const int tid = threadIdx.x;
    sh[tid] = g_partial[tid];
    __syncthreads();
#pragma unroll
    for (int o = 512; o > 0; o >>= 1) {
        if (tid < o) sh[tid] += sh[tid + o];
        __syncthreads();
    }
    if (tid == 0) out[0] = sh[0] * (1.0f / (float)(N * KK * 10));
}

// ---------------- launcher ----------------
extern "C" void kernel_launch(void* const* d_in, const int* in_sizes, int n_in,
                              void* d_out, int out_size) {
    const float* X = (const float*)d_in[0];
    const float* Z = (const float*)d_in[1];
    if (n_in >= 2 && in_sizes[0] == N * DZ && in_sizes[1] == N * DX) {
        X = (const float*)d_in[1];
        Z = (const float*)d_in[0];
    }
    float* out = (float*)d_out;

    const int smem_bytes = (2 * BK * TIP * 2 + TI * TJP + TJ) * (int)sizeof(float);
    cudaFuncSetAttribute(knn_kernel, cudaFuncAttributeMaxDynamicSharedMemorySize, smem_bytes);

    sqx_kernel<<<N / 8, 256>>>(X);
    knn_kernel<<<dim3(IBLOCKS, JSPLIT), 256, smem_bytes>>>(X);
    final_kernel<<<N / 8, 256>>>(Z);
    reduce_kernel<<<1, 1024>>>(out);
}

// round 11
// speedup vs baseline: 1.4096x; 1.4096x over previous
#include <cuda_runtime.h>
#include <cuda_bf16.h>
#include <math.h>
#include <stdint.h>

#define N       8192
#define DX      256
#define DZ      64
#define KK      5
#define EPSF    1e-7f

#define DXP     768            // packed K: [hi|lo|hi] / [hi|hi|lo]
#define BKE     32             // K elements per chunk
#define NCH     (DXP / BKE)    // 24 chunks
#define TI      128
#define TJ      128
#define JSPLIT  4
#define JCHUNK  (N / JSPLIT)   // 2048
#define JTILES  (JCHUNK / TJ)  // 16
#define IBLOCKS (N / TI)       // 64
#define NSETS   JSPLIT

// smem layout (bytes): padded rows of 80B for ldmatrix conflict-freedom
#define ROWB     80
#define CHUNKB   (TI * ROWB)             // 10240
#define SM_AS    0
#define SM_BS    (2 * CHUNKB)            // 20480
#define SM_DS    (4 * CHUNKB)            // 40960
#define DSTRIDE  130                     // floats per Ds row
#define SM_SQJ   (SM_DS + TI * DSTRIDE * 4)   // 107520
#define SM_TOTAL (SM_SQJ + TJ * 4)            // 108032

// ---- static device scratch ----
__device__ __align__(16) unsigned short g_A[N * DXP];
__device__ __align__(16) unsigned short g_B[N * DXP];
__device__ float g_sqX[N];
__device__ float g_topv[NSETS * N * KK];
__device__ int   g_topi[NSETS * N * KK];
__device__ float g_partial[N / 8];

__device__ __forceinline__ uint32_t smem_u32(const void* p) {
    uint32_t a;
    asm("{ .reg .u64 t; cvta.to.shared.u64 t, %1; cvt.u32.u64 %0, t; }" : "=r"(a) : "l"(p));
    return a;
}

#define LDMX4(r0, r1, r2, r3, a) \
    asm volatile("ldmatrix.sync.aligned.m8n8.x4.shared.b16 {%0,%1,%2,%3}, [%4];" \
        : "=r"(r0), "=r"(r1), "=r"(r2), "=r"(r3) : "r"(a))

#define MMA16816(c, a0, a1, a2, a3, b0, b1) \
    asm volatile("mma.sync.aligned.m16n8k16.row.col.f32.bf16.bf16.f32 " \
        "{%0,%1,%2,%3}, {%4,%5,%6,%7}, {%8,%9}, {%0,%1,%2,%3};" \
        : "+f"((c)[0]), "+f"((c)[1]), "+f"((c)[2]), "+f"((c)[3]) \
        : "r"(a0), "r"(a1), "r"(a2), "r"(a3), "r"(b0), "r"(b1))

// ================= kernel 0: split-bf16 packing =================
__global__ void prep_kernel(const float* __restrict__ X) {
    const int t   = threadIdx.x;
    const int row = blockIdx.x * 4 + (t >> 6);
    const int c4  = t & 63;
    float4 x = *(const float4*)(X + (size_t)row * DX + c4 * 4);
    ushort4 hi, lo;
    __nv_bfloat16 h;
    h = __float2bfloat16_rn(x.x); hi.x = *(unsigned short*)&h;
    { __nv_bfloat16 l = __float2bfloat16_rn(x.x - __bfloat162float(h)); lo.x = *(unsigned short*)&l; }
    h = __float2bfloat16_rn(x.y); hi.y = *(unsigned short*)&h;
    { __nv_bfloat16 l = __float2bfloat16_rn(x.y - __bfloat162float(h)); lo.y = *(unsigned short*)&l; }
    h = __float2bfloat16_rn(x.z); hi.z = *(unsigned short*)&h;
    { __nv_bfloat16 l = __float2bfloat16_rn(x.z - __bfloat162float(h)); lo.z = *(unsigned short*)&l; }
    h = __float2bfloat16_rn(x.w); hi.w = *(unsigned short*)&h;
    { __nv_bfloat16 l = __float2bfloat16_rn(x.w - __bfloat162float(h)); lo.w = *(unsigned short*)&l; }
    const size_t base = (size_t)row * DXP + c4 * 4;
    *(ushort4*)(g_A + base)       = hi;   // A = [hi | lo | hi]
    *(ushort4*)(g_A + base + 256) = lo;
    *(ushort4*)(g_A + base + 512) = hi;
    *(ushort4*)(g_B + base)       = hi;   // B = [hi | hi | lo]
    *(ushort4*)(g_B + base + 256) = hi;
    *(ushort4*)(g_B + base + 512) = lo;
}

// ================= kernel 1: row squared norms =================
__global__ void sqx_kernel(const float* __restrict__ X) {
    int row  = blockIdx.x * 8 + (threadIdx.x >> 5);
    int lane = threadIdx.x & 31;
    const float4* xr = reinterpret_cast<const float4*>(X + (size_t)row * DX);
    float s = 0.f;
#pragma unroll
    for (int t = 0; t < 2; ++t) {
        float4 v = xr[lane + 32 * t];
        s += v.x * v.x + v.y * v.y + v.z * v.z + v.w * v.w;
    }
#pragma unroll
    for (int o = 16; o > 0; o >>= 1) s += __shfl_down_sync(0xffffffffu, s, o);
    if (lane == 0) g_sqX[row] = s;
}

// ---------------- top-5 sorted insert ----------------
__device__ __forceinline__ void topk_insert(float (&bv)[KK], int (&bi)[KK], float v, int j) {
    if (v < bv[KK - 1]) {
        bv[KK - 1] = v; bi[KK - 1] = j;
#pragma unroll
        for (int q = KK - 1; q > 0; --q) {
            if (bv[q] < bv[q - 1]) {
                float tv = bv[q]; bv[q] = bv[q - 1]; bv[q - 1] = tv;
                int   tj = bi[q]; bi[q] = bi[q - 1]; bi[q - 1] = tj;
            }
        }
    }
}

// ================= kernel 2: mma.sync Gram + fused top-5 =================
__global__ __launch_bounds__(256, 1)
void knn_mma_kernel() {
    extern __shared__ char smem[];
    const uint32_t sb = smem_u32(smem);
    float* Ds  = (float*)(smem + SM_DS);
    float* sqj = (float*)(smem + SM_SQJ);

    const int tid  = threadIdx.x;
    const int wid  = tid >> 5;
    const int lane = tid & 31;
    const int wm   = wid & 1;          // warp m 0..1 (64 rows each)
    const int wn   = wid >> 1;         // warp n 0..3 (32 cols each)
    const int i0    = blockIdx.x * TI;
    const int jbase = blockIdx.y * JCHUNK;
    const float FINF = __int_as_float(0x7f800000);

    // ldmatrix lane addressing (constant per thread)
    const int a_row = lane & 15;                 // + kbyte (lane>>4)*16
    const int a_kb  = (lane >> 4) * 16;
    const int bg    = lane >> 3;
    const int b_row = ((bg >> 1) * 8) + (lane & 7);
    const int b_kb  = (bg & 1) * 16;

    float bv[KK]; int bi[KK];
#pragma unroll
    for (int q = 0; q < KK; ++q) { bv[q] = FINF; bi[q] = 0; }

    for (int jt = 0; jt < JTILES; ++jt) {
        const int j0 = jbase + jt * TJ;
        if (tid < TJ) sqj[tid] = g_sqX[j0 + tid];

        float c[4][4][4];
#pragma unroll
        for (int mi = 0; mi < 4; ++mi)
#pragma unroll
            for (int ni = 0; ni < 4; ++ni)
#pragma unroll
                for (int r = 0; r < 4; ++r) c[mi][ni][r] = 0.f;

        // prologue: load chunk 0 into buffer 0
        {
#pragma unroll
            for (int s = 0; s < 2; ++s) {
                int idx = tid + s * 256, row = idx >> 2, seg = idx & 3;
                uint4 va = *(const uint4*)(g_A + (size_t)(i0 + row) * DXP + seg * 8);
                uint4 vb = *(const uint4*)(g_B + (size_t)(j0 + row) * DXP + seg * 8);
                *(uint4*)(smem + SM_AS + row * ROWB + seg * 16) = va;
                *(uint4*)(smem + SM_BS + row * ROWB + seg * 16) = vb;
            }
        }
        __syncthreads();

        for (int kc = 0; kc < NCH; ++kc) {
            const int cur = kc & 1;
            uint4 pa[2], pb[2];
            if (kc + 1 < NCH) {
                const int kk = (kc + 1) * BKE;
#pragma unroll
                for (int s = 0; s < 2; ++s) {
                    int idx = tid + s * 256, row = idx >> 2, seg = idx & 3;
                    pa[s] = *(const uint4*)(g_A + (size_t)(i0 + row) * DXP + kk + seg * 8);
                    pb[s] = *(const uint4*)(g_B + (size_t)(j0 + row) * DXP + kk + seg * 8);
                }
            }

            // MMA on current buffer: 2 k16 steps
            const uint32_t abase = sb + SM_AS + cur * CHUNKB + (wm * 64 + a_row) * ROWB + a_kb;
            const uint32_t bbase = sb + SM_BS + cur * CHUNKB + (wn * 32 + b_row) * ROWB + b_kb;
#pragma unroll
            for (int s = 0; s < 2; ++s) {
                uint32_t af[4][4];
#pragma unroll
                for (int mi = 0; mi < 4; ++mi)
                    LDMX4(af[mi][0], af[mi][1], af[mi][2], af[mi][3],
                          abase + mi * 16 * ROWB + s * 32);
                uint32_t bf[2][4];
#pragma unroll
                for (int nh = 0; nh < 2; ++nh)
                    LDMX4(bf[nh][0], bf[nh][1], bf[nh][2], bf[nh][3],
                          bbase + nh * 16 * ROWB + s * 32);
#pragma unroll
                for (int mi = 0; mi < 4; ++mi) {
#pragma unroll
                    for (int ni = 0; ni < 4; ++ni) {
                        const uint32_t* bq = bf[ni >> 1];
                        const int o = (ni & 1) * 2;
                        MMA16816(c[mi][ni], af[mi][0], af[mi][1], af[mi][2], af[mi][3],
                                 bq[o], bq[o + 1]);
                    }
                }
            }

            if (kc + 1 < NCH) {
                const int nb = cur ^ 1;
#pragma unroll
                for (int s = 0; s < 2; ++s) {
                    int idx = tid + s * 256, row = idx >> 2, seg = idx & 3;
                    *(uint4*)(smem + SM_AS + nb * CHUNKB + row * ROWB + seg * 16) = pa[s];
                    *(uint4*)(smem + SM_BS + nb * CHUNKB + row * ROWB + seg * 16) = pb[s];
                }
            }
            __syncthreads();
        }

        // writer: halfval = 0.5*sq[j] - dot into Ds
        {
            const int g    = lane >> 2;
            const int cpair = (lane & 3) * 2;
#pragma unroll
            for (int mi = 0; mi < 4; ++mi) {
                const int r0 = wm * 64 + mi * 16 + g;
#pragma unroll
                for (int ni = 0; ni < 4; ++ni) {
                    const int col = wn * 32 + ni * 8 + cpair;
                    const float s0 = sqj[col], s1 = sqj[col + 1];
                    float2 lo = make_float2(fmaf(0.5f, s0, -c[mi][ni][0]),
                                            fmaf(0.5f, s1, -c[mi][ni][1]));
                    float2 hi = make_float2(fmaf(0.5f, s0, -c[mi][ni][2]),
                                            fmaf(0.5f, s1, -c[mi][ni][3]));
                    *(float2*)&Ds[r0 * DSTRIDE + col]       = lo;
                    *(float2*)&Ds[(r0 + 8) * DSTRIDE + col] = hi;
                }
            }
        }
        __syncthreads();

        // scan: 128 threads, one per row, persistent top-5
        if (tid < TI) {
            const float* drow = Ds + tid * DSTRIDE;
            const int selfcol = (i0 + tid) - j0;
#pragma unroll 4
            for (int e = 0; e < TJ; ++e) {
                float v = drow[e];
                if (v < bv[KK - 1] && e != selfcol)
                    topk_insert(bv, bi, v, j0 + e);
            }
        }
        __syncthreads();
    }

    if (tid < TI) {
        const int row  = i0 + tid;
        const int base = (blockIdx.y * N + row) * KK;
#pragma unroll
        for (int q = 0; q < KK; ++q) {
            g_topv[base + q] = bv[q];
            g_topi[base + q] = bi[q];
        }
    }
}

// ================= kernel 3: merge + LID + partial sums =================
__global__ void final_kernel(const float* __restrict__ Z) {
    const int warp = threadIdx.x >> 5;
    const int lane = threadIdx.x & 31;
    const int row  = blockIdx.x * 8 + warp;
    const float FINF = __int_as_float(0x7f800000);

    float bv[KK]; int bi[KK];
#pragma unroll
    for (int q = 0; q < KK; ++q) { bv[q] = FINF; bi[q] = 0; }
    for (int s = 0; s < NSETS; ++s) {
        const int base = (s * N + row) * KK;
#pragma unroll
        for (int q = 0; q < KK; ++q)
            topk_insert(bv, bi, g_topv[base + q], g_topi[base + q]);
    }

    const float sqi = g_sqX[row];
    float vx[KK];
#pragma unroll
    for (int q = 0; q < KK; ++q) {
        float d2 = fmaxf(fmaf(2.f, bv[q], sqi), 0.f);
        vx[q] = sqrtf(d2) + EPSF;
    }
    float lidX = 0.f;
    {
        float l4 = log10f(vx[KK - 1]);
#pragma unroll
        for (int q = 0; q < KK; ++q) lidX += l4 - log10f(vx[q]);
    }

    const float zi0 = Z[(size_t)row * DZ + lane];
    const float zi1 = Z[(size_t)row * DZ + 32 + lane];
    float ez[KK];
#pragma unroll
    for (int q = 0; q < KK; ++q) {
        const int j = bi[q];
        float d0 = zi0 - Z[(size_t)j * DZ + lane];
        float d1 = zi1 - Z[(size_t)j * DZ + 32 + lane];
        float s = d0 * d0 + d1 * d1;
#pragma unroll
        for (int o = 16; o > 0; o >>= 1) s += __shfl_xor_sync(0xffffffffu, s, o);
        ez[q] = sqrtf(s) + EPSF;
    }
    float lidZ = 0.f;
    {
        float l4 = log10f(ez[KK - 1]);
#pragma unroll
        for (int q = 0; q < KK; ++q) lidZ += l4 - log10f(ez[q]);
    }

    float diff = lidX - lidZ;
    float val  = diff * diff;

    __shared__ float ws[8];
    if (lane == 0) ws[warp] = val;
    __syncthreads();
    if (threadIdx.x == 0) {
        float s = 0.f;
#pragma unroll
        for (int w = 0; w < 8; ++w) s += ws[w];
        g_partial[blockIdx.x] = s;
    }
}

// ================= kernel 4: deterministic reduction =================
__global__ void reduce_kernel(float* __restrict__ out) {
    __shared__ float sh[1024];
    const int tid = threadIdx.x;
    sh[tid] = g_partial[tid];
    __syncthreads();
#pragma unroll
    for (int o = 512; o > 0; o >>= 1) {
        if (tid < o) sh[tid] += sh[tid + o];
        __syncthreads();
    }
    if (tid == 0) out[0] = sh[0] * (1.0f / (float)(N * KK * 10));
}

// ================= launcher =================
extern "C" void kernel_launch(void* const* d_in, const int* in_sizes, int n_in,
                              void* d_out, int out_size) {
    const float* X = (const float*)d_in[0];
    const float* Z = (const float*)d_in[1];
    if (n_in >= 2 && in_sizes[0] == N * DZ && in_sizes[1] == N * DX) {
        X = (const float*)d_in[1];
        Z = (const float*)d_in[0];
    }
    float* out = (float*)d_out;

    cudaFuncSetAttribute(knn_mma_kernel, cudaFuncAttributeMaxDynamicSharedMemorySize, SM_TOTAL);

    prep_kernel<<<N / 4, 256>>>(X);
    sqx_kernel<<<N / 8, 256>>>(X);
    knn_mma_kernel<<<dim3(IBLOCKS, JSPLIT), 256, SM_TOTAL>>>();
    final_kernel<<<N / 8, 256>>>(Z);
    reduce_kernel<<<1, 1024>>>(out);
}

// round 17
// speedup vs baseline: 1.5176x; 1.0766x over previous
#include <cuda_runtime.h>
#include <cuda_bf16.h>
#include <math.h>
#include <stdint.h>

#define N       8192
#define DX      256
#define DZ      64
#define KK      5
#define EPSF    1e-7f

#define DXP     768            // packed K: [hi|lo|hi] / [hi|hi|lo]
#define BKE     64             // K elements per chunk (128 B rows)
#define NCH     (DXP / BKE)    // 12 chunks
#define TI      128
#define TJ      128
#define JSPLIT  4
#define JCHUNK  (N / JSPLIT)   // 2048
#define JTILES  (JCHUNK / TJ)  // 16
#define IBLOCKS (N / TI)       // 64
#define NSETS   JSPLIT

// smem: 3-stage A/B buffers, 144B padded rows (128B data + 16B pad)
#define ROWB     144
#define STAGEB   (TI * ROWB)                 // 18432
#define SM_AS    0                            // 3 stages: 0..55296
#define SM_BS    (3 * STAGEB)                 // 55296..110592
#define SM_DS    (6 * STAGEB)                 // 110592
#define DSTRIDE  130
#define SM_SQJ   (SM_DS + TI * DSTRIDE * 4)   // 177152
#define SM_TOTAL (SM_SQJ + TJ * 4)            // 177664

// ---- static device scratch ----
__device__ __align__(16) unsigned short g_A[N * DXP];
__device__ __align__(16) unsigned short g_B[N * DXP];
__device__ float g_sqX[N];
__device__ float g_topv[NSETS * N * KK];
__device__ int   g_topi[NSETS * N * KK];
__device__ float g_partial[N / 8];

__device__ __forceinline__ uint32_t smem_u32(const void* p) {
    uint32_t a;
    asm("{ .reg .u64 t; cvta.to.shared.u64 t, %1; cvt.u32.u64 %0, t; }" : "=r"(a) : "l"(p));
    return a;
}

#define CPASYNC16(dst, src) \
    asm volatile("cp.async.cg.shared.global [%0], [%1], 16;" :: "r"(dst), "l"(src) : "memory")
#define CP_COMMIT() asm volatile("cp.async.commit_group;" ::: "memory")

#define LDMX4(r0, r1, r2, r3, a) \
    asm volatile("ldmatrix.sync.aligned.m8n8.x4.shared.b16 {%0,%1,%2,%3}, [%4];" \
        : "=r"(r0), "=r"(r1), "=r"(r2), "=r"(r3) : "r"(a))

#define MMA16816(c, a0, a1, a2, a3, b0, b1) \
    asm volatile("mma.sync.aligned.m16n8k16.row.col.f32.bf16.bf16.f32 " \
        "{%0,%1,%2,%3}, {%4,%5,%6,%7}, {%8,%9}, {%0,%1,%2,%3};" \
        : "+f"((c)[0]), "+f"((c)[1]), "+f"((c)[2]), "+f"((c)[3]) \
        : "r"(a0), "r"(a1), "r"(a2), "r"(a3), "r"(b0), "r"(b1))

// ================= kernel 0: split-bf16 packing =================
__global__ void prep_kernel(const float* __restrict__ X) {
    const int t   = threadIdx.x;
    const int row = blockIdx.x * 4 + (t >> 6);
    const int c4  = t & 63;
    float4 x = *(const float4*)(X + (size_t)row * DX + c4 * 4);
    ushort4 hi, lo;
    __nv_bfloat16 h;
    h = __float2bfloat16_rn(x.x); hi.x = *(unsigned short*)&h;
    { __nv_bfloat16 l = __float2bfloat16_rn(x.x - __bfloat162float(h)); lo.x = *(unsigned short*)&l; }
    h = __float2bfloat16_rn(x.y); hi.y = *(unsigned short*)&h;
    { __nv_bfloat16 l = __float2bfloat16_rn(x.y - __bfloat162float(h)); lo.y = *(unsigned short*)&l; }
    h = __float2bfloat16_rn(x.z); hi.z = *(unsigned short*)&h;
    { __nv_bfloat16 l = __float2bfloat16_rn(x.z - __bfloat162float(h)); lo.z = *(unsigned short*)&l; }
    h = __float2bfloat16_rn(x.w); hi.w = *(unsigned short*)&h;
    { __nv_bfloat16 l = __float2bfloat16_rn(x.w - __bfloat162float(h)); lo.w = *(unsigned short*)&l; }
    const size_t base = (size_t)row * DXP + c4 * 4;
    *(ushort4*)(g_A + base)       = hi;   // A = [hi | lo | hi]
    *(ushort4*)(g_A + base + 256) = lo;
    *(ushort4*)(g_A + base + 512) = hi;
    *(ushort4*)(g_B + base)       = hi;   // B = [hi | hi | lo]
    *(ushort4*)(g_B + base + 256) = hi;
    *(ushort4*)(g_B + base + 512) = lo;
}

// ================= kernel 1: row squared norms =================
__global__ void sqx_kernel(const float* __restrict__ X) {
    int row  = blockIdx.x * 8 + (threadIdx.x >> 5);
    int lane = threadIdx.x & 31;
    const float4* xr = reinterpret_cast<const float4*>(X + (size_t)row * DX);
    float s = 0.f;
#pragma unroll
    for (int t = 0; t < 2; ++t) {
        float4 v = xr[lane + 32 * t];
        s += v.x * v.x + v.y * v.y + v.z * v.z + v.w * v.w;
    }
#pragma unroll
    for (int o = 16; o > 0; o >>= 1) s += __shfl_down_sync(0xffffffffu, s, o);
    if (lane == 0) g_sqX[row] = s;
}

// dummy kernel: positions knn at the ncu capture slot
__global__ void dummy_kernel() {}

// ---------------- top-5 sorted insert ----------------
__device__ __forceinline__ void topk_insert(float (&bv)[KK], int (&bi)[KK], float v, int j) {
    if (v < bv[KK - 1]) {
        bv[KK - 1] = v; bi[KK - 1] = j;
#pragma unroll
        for (int q = KK - 1; q > 0; --q) {
            if (bv[q] < bv[q - 1]) {
                float tv = bv[q]; bv[q] = bv[q - 1]; bv[q - 1] = tv;
                int   tj = bi[q]; bi[q] = bi[q - 1]; bi[q - 1] = tj;
            }
        }
    }
}

// ================= kernel 2: mma.sync Gram + fused top-5, cp.async 3-stage =================
__global__ __launch_bounds__(256, 1)
void knn_mma_kernel() {
    extern __shared__ char smem[];
    const uint32_t sb = smem_u32(smem);
    float* Ds  = (float*)(smem + SM_DS);
    float* sqj = (float*)(smem + SM_SQJ);

    const int tid  = threadIdx.x;
    const int wid  = tid >> 5;
    const int lane = tid & 31;
    const int wm   = wid & 1;          // warp m 0..1 (64 rows each)
    const int wn   = wid >> 1;         // warp n 0..3 (32 cols each)
    const int i0    = blockIdx.x * TI;
    const int jbase = blockIdx.y * JCHUNK;
    const float FINF = __int_as_float(0x7f800000);

    const int a_row = lane & 15;
    const int a_kb  = (lane >> 4) * 16;
    const int bg    = lane >> 3;
    const int b_row = ((bg >> 1) * 8) + (lane & 7);
    const int b_kb  = (bg & 1) * 16;

    float bv[KK]; int bi[KK];
#pragma unroll
    for (int q = 0; q < KK; ++q) { bv[q] = FINF; bi[q] = 0; }

    for (int jt = 0; jt < JTILES; ++jt) {
        const int j0 = jbase + jt * TJ;
        if (tid < TJ) sqj[tid] = g_sqX[j0 + tid];

        float c[4][4][4];
#pragma unroll
        for (int mi = 0; mi < 4; ++mi)
#pragma unroll
            for (int ni = 0; ni < 4; ++ni)
#pragma unroll
                for (int r = 0; r < 4; ++r) c[mi][ni][r] = 0.f;

        // prologue: issue chunks 0,1 into stages 0,1
#pragma unroll
        for (int pc = 0; pc < 2; ++pc) {
            const int kk = pc * BKE;
#pragma unroll
            for (int s = 0; s < 4; ++s) {
                int idx = tid + s * 256, row = idx >> 3, seg = idx & 7;
                CPASYNC16(sb + SM_AS + pc * STAGEB + row * ROWB + seg * 16,
                          g_A + (size_t)(i0 + row) * DXP + kk + seg * 8);
                CPASYNC16(sb + SM_BS + pc * STAGEB + row * ROWB + seg * 16,
                          g_B + (size_t)(j0 + row) * DXP + kk + seg * 8);
            }
            CP_COMMIT();
        }

        for (int kc = 0; kc < NCH; ++kc) {
            if (kc < NCH - 1) asm volatile("cp.async.wait_group 1;" ::: "memory");
            else              asm volatile("cp.async.wait_group 0;" ::: "memory");
            __syncthreads();

            if (kc + 2 < NCH) {
                const int st = (kc + 2) % 3;
                const int kk = (kc + 2) * BKE;
#pragma unroll
                for (int s = 0; s < 4; ++s) {
                    int idx = tid + s * 256, row = idx >> 3, seg = idx & 7;
                    CPASYNC16(sb + SM_AS + st * STAGEB + row * ROWB + seg * 16,
                              g_A + (size_t)(i0 + row) * DXP + kk + seg * 8);
                    CPASYNC16(sb + SM_BS + st * STAGEB + row * ROWB + seg * 16,
                              g_B + (size_t)(j0 + row) * DXP + kk + seg * 8);
                }
                CP_COMMIT();
            }

            const int st = kc % 3;
            const uint32_t abase = sb + SM_AS + st * STAGEB + (wm * 64 + a_row) * ROWB + a_kb;
            const uint32_t bbase = sb + SM_BS + st * STAGEB + (wn * 32 + b_row) * ROWB + b_kb;
#pragma unroll
            for (int s = 0; s < 4; ++s) {
                uint32_t af[4][4];
#pragma unroll
                for (int mi = 0; mi < 4; ++mi)
                    LDMX4(af[mi][0], af[mi][1], af[mi][2], af[mi][3],
                          abase + mi * 16 * ROWB + s * 32);
                uint32_t bf[2][4];
#pragma unroll
                for (int nh = 0; nh < 2; ++nh)
                    LDMX4(bf[nh][0], bf[nh][1], bf[nh][2], bf[nh][3],
                          bbase + nh * 16 * ROWB + s * 32);
#pragma unroll
                for (int mi = 0; mi < 4; ++mi) {
#pragma unroll
                    for (int ni = 0; ni < 4; ++ni) {
                        const uint32_t* bq = bf[ni >> 1];
                        const int o = (ni & 1) * 2;
                        MMA16816(c[mi][ni], af[mi][0], af[mi][1], af[mi][2], af[mi][3],
                                 bq[o], bq[o + 1]);
                    }
                }
            }
        }

        // writer: halfval = 0.5*sq[j] - dot into Ds
        {
            const int g     = lane >> 2;
            const int cpair = (lane & 3) * 2;
#pragma unroll
            for (int mi = 0; mi < 4; ++mi) {
                const int r0 = wm * 64 + mi * 16 + g;
#pragma unroll
                for (int ni = 0; ni < 4; ++ni) {
                    const int col = wn * 32 + ni * 8 + cpair;
                    const float s0 = sqj[col], s1 = sqj[col + 1];
                    float2 lo = make_float2(fmaf(0.5f, s0, -c[mi][ni][0]),
                                            fmaf(0.5f, s1, -c[mi][ni][1]));
                    float2 hi = make_float2(fmaf(0.5f, s0, -c[mi][ni][2]),
                                            fmaf(0.5f, s1, -c[mi][ni][3]));
                    *(float2*)&Ds[r0 * DSTRIDE + col]       = lo;
                    *(float2*)&Ds[(r0 + 8) * DSTRIDE + col] = hi;
                }
            }
        }
        __syncthreads();

        // scan: 128 threads, one per row, persistent top-5
        if (tid < TI) {
            const float* drow = Ds + tid * DSTRIDE;
            const int selfcol = (i0 + tid) - j0;
#pragma unroll 4
            for (int e = 0; e < TJ; ++e) {
                float v = drow[e];
                if (v < bv[KK - 1] && e != selfcol)
                    topk_insert(bv, bi, v, j0 + e);
            }
        }
        __syncthreads();
    }

    if (tid < TI) {
        const int row  = i0 + tid;
        const int base = (blockIdx.y * N + row) * KK;
#pragma unroll
        for (int q = 0; q < KK; ++q) {
            g_topv[base + q] = bv[q];
            g_topi[base + q] = bi[q];
        }
    }
}

// ================= kernel 3: merge + LID + partial sums =================
__global__ void final_kernel(const float* __restrict__ Z) {
    const int warp = threadIdx.x >> 5;
    const int lane = threadIdx.x & 31;
    const int row  = blockIdx.x * 8 + warp;
    const float FINF = __int_as_float(0x7f800000);

    float bv[KK]; int bi[KK];
#pragma unroll
    for (int q = 0; q < KK; ++q) { bv[q] = FINF; bi[q] = 0; }
    for (int s = 0; s < NSETS; ++s) {
        const int base = (s * N + row) * KK;
#pragma unroll
        for (int q = 0; q < KK; ++q)
            topk_insert(bv, bi, g_topv[base + q], g_topi[base + q]);
    }

    const float sqi = g_sqX[row];
    float vx[KK];
#pragma unroll
    for (int q = 0; q < KK; ++q) {
        float d2 = fmaxf(fmaf(2.f, bv[q], sqi), 0.f);
        vx[q] = sqrtf(d2) + EPSF;
    }
    float lidX = 0.f;
    {
        float l4 = log10f(vx[KK - 1]);
#pragma unroll
        for (int q = 0; q < KK; ++q) lidX += l4 - log10f(vx[q]);
    }

    const float zi0 = Z[(size_t)row * DZ + lane];
    const float zi1 = Z[(size_t)row * DZ + 32 + lane];
    float ez[KK];
#pragma unroll
    for (int q = 0; q < KK; ++q) {
        const int j = bi[q];
        float d0 = zi0 - Z[(size_t)j * DZ + lane];
        float d1 = zi1 - Z[(size_t)j * DZ + 32 + lane];
        float s = d0 * d0 + d1 * d1;
#pragma unroll
        for (int o = 16; o > 0; o >>= 1) s += __shfl_xor_sync(0xffffffffu, s, o);
        ez[q] = sqrtf(s) + EPSF;
    }
    float lidZ = 0.f;
    {
        float l4 = log10f(ez[KK - 1]);
#pragma unroll
        for (int q = 0; q < KK; ++q) lidZ += l4 - log10f(ez[q]);
    }

    float diff = lidX - lidZ;
    float val  = diff * diff;

    __shared__ float ws[8];
    if (lane == 0) ws[warp] = val;
    __syncthreads();
    if (threadIdx.x == 0) {
        float s = 0.f;
#pragma unroll
        for (int w = 0; w < 8; ++w) s += ws[w];
        g_partial[blockIdx.x] = s;
    }
}

// ================= kernel 4: deterministic reduction =================
__global__ void reduce_kernel(float* __restrict__ out) {
    __shared__ float sh[1024];
    const int tid = threadIdx.x;
    sh[tid] = g_partial[tid];
    __syncthreads();
#pragma unroll
    for (int o = 512; o > 0; o >>= 1) {
        if (tid < o) sh[tid] += sh[tid + o];
        __syncthreads();
    }
    if (tid == 0) out[0] = sh[0] * (1.0f / (float)(N * KK * 10));
}

// ================= launcher =================
extern "C" void kernel_launch(void* const* d_in, const int* in_sizes, int n_in,
                              void* d_out, int out_size) {
    const float* X = (const float*)d_in[0];
    const float* Z = (const float*)d_in[1];
    if (n_in >= 2 && in_sizes[0] == N * DZ && in_sizes[1] == N * DX) {
        X = (const float*)d_in[1];
        Z = (const float*)d_in[0];
    }
    float* out = (float*)d_out;

    cudaFuncSetAttribute(knn_mma_kernel, cudaFuncAttributeMaxDynamicSharedMemorySize, SM_TOTAL);

    prep_kernel<<<N / 4, 256>>>(X);
    sqx_kernel<<<N / 8, 256>>>(X);
    dummy_kernel<<<1, 32>>>();
    knn_mma_kernel<<<dim3(IBLOCKS, JSPLIT), 256, SM_TOTAL>>>();
    final_kernel<<<N / 8, 256>>>(Z);
    reduce_kernel<<<1, 1024>>>(out);
}